// round 3
// baseline (speedup 1.0000x reference)
#include <cuda_runtime.h>
#include <cstdint>

#define N_NODE 100000
#define N_TOT  102000
#define NFEAT  256
#define NDIM   128

// ---------------------------------------------------------------------------
// zero x2/x3 regions
// ---------------------------------------------------------------------------
__global__ void zero_kernel(float* __restrict__ p, size_t n4) {
    size_t i = (size_t)blockIdx.x * blockDim.x + threadIdx.x;
    size_t stride = (size_t)gridDim.x * blockDim.x;
    float4* p4 = (float4*)p;
    for (size_t j = i; j < n4; j += stride)
        p4[j] = make_float4(0.f, 0.f, 0.f, 0.f);
}

// ---------------------------------------------------------------------------
// x1 = concat(emb_node, emb_attri) @ W1^T  via 3xTF32 mma.sync.m16n8k8
// BM=128, BN=128 (full width), BK=16. 256 threads = 8 warps in 4(M) x 2(N).
// Each warp: 32(M) x 64(N) = 2 m-tiles x 8 n-tiles.
// hi/lo tf32 split precomputed into smem at tile-load time.
// ---------------------------------------------------------------------------
#define BK 16
#define LDS_STRIDE 136   // 128 + 8 pad -> conflict-free fragment loads

__device__ __forceinline__ uint32_t f2tf32(float x) {
    uint32_t r;
    asm("cvt.rna.tf32.f32 %0, %1;" : "=r"(r) : "f"(x));
    return r;
}

__device__ __forceinline__ void mma_tf32(
    float& d0, float& d1, float& d2, float& d3,
    uint32_t a0, uint32_t a1, uint32_t a2, uint32_t a3,
    uint32_t b0, uint32_t b1)
{
    asm volatile(
        "mma.sync.aligned.m16n8k8.row.col.f32.tf32.tf32.f32 "
        "{%0,%1,%2,%3},{%4,%5,%6,%7},{%8,%9},{%0,%1,%2,%3};"
        : "+f"(d0), "+f"(d1), "+f"(d2), "+f"(d3)
        : "r"(a0), "r"(a1), "r"(a2), "r"(a3), "r"(b0), "r"(b1));
}

__global__ __launch_bounds__(256) void gemm_kernel(
    const float* __restrict__ A0,   // emb_node  [100000, 256]
    const float* __restrict__ A1,   // emb_attri [2000, 256]
    const float* __restrict__ W,    // W1 [128, 256]
    float* __restrict__ C)          // x1 [N_TOT, 128]
{
    __shared__ uint32_t Ah[BK][LDS_STRIDE];
    __shared__ uint32_t Al[BK][LDS_STRIDE];
    __shared__ uint32_t Wh[BK][LDS_STRIDE];
    __shared__ uint32_t Wl[BK][LDS_STRIDE];

    const int t    = threadIdx.x;
    const int lane = t & 31;
    const int wid  = t >> 5;
    const int warpM = (wid & 3) * 32;   // 4 warps over M
    const int warpN = (wid >> 2) * 64;  // 2 warps over N
    const int l4 = lane & 3;
    const int lq = lane >> 2;
    const int blockRow = blockIdx.x * 128;

    float acc[2][8][4];
#pragma unroll
    for (int mt = 0; mt < 2; mt++)
#pragma unroll
        for (int nt = 0; nt < 8; nt++)
#pragma unroll
            for (int r = 0; r < 4; r++) acc[mt][nt][r] = 0.f;

    // tile-load addressing: 2 float4 per thread per operand
    const int lr0 = t >> 2;               // 0..63
    const int lkq = (t & 3) << 2;         // 0,4,8,12

    for (int kk = 0; kk < NFEAT; kk += BK) {
        // ---- load + split A tile (128 x 16) ----
#pragma unroll
        for (int h = 0; h < 2; h++) {
            int r = lr0 + h * 64;         // 0..127
            int grow = blockRow + r;
            float4 v = make_float4(0.f, 0.f, 0.f, 0.f);
            if (grow < N_TOT) {
                const float* src = (grow < N_NODE)
                    ? (A0 + (size_t)grow * NFEAT)
                    : (A1 + (size_t)(grow - N_NODE) * NFEAT);
                v = *(const float4*)(src + kk + lkq);
            }
            float e[4] = {v.x, v.y, v.z, v.w};
#pragma unroll
            for (int i = 0; i < 4; i++) {
                uint32_t hi = f2tf32(e[i]);
                float hif = __uint_as_float(hi);
                uint32_t lo = f2tf32(e[i] - hif);
                Ah[lkq + i][r] = hi;
                Al[lkq + i][r] = lo;
            }
        }
        // ---- load + split W tile (128 x 16) ----
#pragma unroll
        for (int h = 0; h < 2; h++) {
            int r = lr0 + h * 64;
            float4 v = *(const float4*)(W + (size_t)r * NFEAT + kk + lkq);
            float e[4] = {v.x, v.y, v.z, v.w};
#pragma unroll
            for (int i = 0; i < 4; i++) {
                uint32_t hi = f2tf32(e[i]);
                float hif = __uint_as_float(hi);
                uint32_t lo = f2tf32(e[i] - hif);
                Wh[lkq + i][r] = hi;
                Wl[lkq + i][r] = lo;
            }
        }
        __syncthreads();

#pragma unroll
        for (int ks = 0; ks < BK; ks += 8) {
            // A fragments for both m-tiles (hi and lo)
            uint32_t ah[2][4], al[2][4];
#pragma unroll
            for (int mt = 0; mt < 2; mt++) {
                int m0 = warpM + mt * 16;
                ah[mt][0] = Ah[ks + l4    ][m0 + lq    ];
                ah[mt][1] = Ah[ks + l4    ][m0 + lq + 8];
                ah[mt][2] = Ah[ks + l4 + 4][m0 + lq    ];
                ah[mt][3] = Ah[ks + l4 + 4][m0 + lq + 8];
                al[mt][0] = Al[ks + l4    ][m0 + lq    ];
                al[mt][1] = Al[ks + l4    ][m0 + lq + 8];
                al[mt][2] = Al[ks + l4 + 4][m0 + lq    ];
                al[mt][3] = Al[ks + l4 + 4][m0 + lq + 8];
            }
#pragma unroll
            for (int nt = 0; nt < 8; nt++) {
                int n0 = warpN + nt * 8;
                uint32_t bh0 = Wh[ks + l4    ][n0 + lq];
                uint32_t bh1 = Wh[ks + l4 + 4][n0 + lq];
                uint32_t bl0 = Wl[ks + l4    ][n0 + lq];
                uint32_t bl1 = Wl[ks + l4 + 4][n0 + lq];
#pragma unroll
                for (int mt = 0; mt < 2; mt++) {
                    float* d = acc[mt][nt];
                    // small terms first, then the dominant one
                    mma_tf32(d[0], d[1], d[2], d[3],
                             al[mt][0], al[mt][1], al[mt][2], al[mt][3], bh0, bh1);
                    mma_tf32(d[0], d[1], d[2], d[3],
                             ah[mt][0], ah[mt][1], ah[mt][2], ah[mt][3], bl0, bl1);
                    mma_tf32(d[0], d[1], d[2], d[3],
                             ah[mt][0], ah[mt][1], ah[mt][2], ah[mt][3], bh0, bh1);
                }
            }
        }
        __syncthreads();
    }

    // ---- epilogue ----
#pragma unroll
    for (int mt = 0; mt < 2; mt++) {
#pragma unroll
        for (int half = 0; half < 2; half++) {
            int row = blockRow + warpM + mt * 16 + lq + half * 8;
            if (row < N_TOT) {
                float* crow = C + (size_t)row * NDIM;
#pragma unroll
                for (int nt = 0; nt < 8; nt++) {
                    int col = warpN + nt * 8 + 2 * l4;
                    float2 v;
                    v.x = acc[mt][nt][half * 2 + 0];
                    v.y = acc[mt][nt][half * 2 + 1];
                    *(float2*)(crow + col) = v;
                }
            }
        }
    }
}

// ---------------------------------------------------------------------------
// SpMM scatter, both adjacencies in one launch. EPW=8 edges/warp (MLP=8).
// ---------------------------------------------------------------------------
#define EPW 8

__global__ __launch_bounds__(256) void scatter2_kernel(
    const float* __restrict__ x1,
    const int*   __restrict__ erow1,
    const int*   __restrict__ ecol1,
    const float* __restrict__ eval1,
    const int*   __restrict__ erow2,
    const int*   __restrict__ ecol2,
    const float* __restrict__ eval2,
    float* __restrict__ x2,
    float* __restrict__ x3,
    int E)
{
    const int warpsPerAdj = (E + EPW - 1) / EPW;
    int gw = (int)(((size_t)blockIdx.x * blockDim.x + threadIdx.x) >> 5);
    const int lane = threadIdx.x & 31;

    const int*   erow;
    const int*   ecol;
    const float* eval;
    float*       out;
    if (gw < warpsPerAdj) {
        erow = erow1; ecol = ecol1; eval = eval1; out = x2;
    } else {
        gw -= warpsPerAdj;
        if (gw >= warpsPerAdj) return;
        erow = erow2; ecol = ecol2; eval = eval2; out = x3;
    }

    const int e0 = gw * EPW;
    int rr[EPW], cc[EPW];
    float vv[EPW];
    int n;
    if (e0 + EPW <= E) {
        n = EPW;
#pragma unroll
        for (int q = 0; q < 2; q++) {
            int4   r4 = *(const int4*)(erow + e0 + q * 4);
            int4   c4 = *(const int4*)(ecol + e0 + q * 4);
            float4 v4 = *(const float4*)(eval + e0 + q * 4);
            rr[q*4+0] = r4.x; rr[q*4+1] = r4.y; rr[q*4+2] = r4.z; rr[q*4+3] = r4.w;
            cc[q*4+0] = c4.x; cc[q*4+1] = c4.y; cc[q*4+2] = c4.z; cc[q*4+3] = c4.w;
            vv[q*4+0] = v4.x; vv[q*4+1] = v4.y; vv[q*4+2] = v4.z; vv[q*4+3] = v4.w;
        }
    } else {
        n = E - e0;
#pragma unroll
        for (int i = 0; i < EPW; i++) {
            if (i < n) {
                rr[i] = __ldg(erow + e0 + i);
                cc[i] = __ldg(ecol + e0 + i);
                vv[i] = __ldg(eval + e0 + i);
            }
        }
    }

    // Phase 1: all gathers in flight (MLP=EPW)
    float4 p[EPW];
#pragma unroll
    for (int i = 0; i < EPW; i++)
        if (i < n)
            p[i] = ((const float4*)(x1 + (size_t)cc[i] * NDIM))[lane];

    // Phase 2: scale + vector reductions
#pragma unroll
    for (int i = 0; i < EPW; i++) {
        if (i < n) {
            float* dst = out + (size_t)rr[i] * NDIM + lane * 4;
            asm volatile("red.global.add.v4.f32 [%0], {%1, %2, %3, %4};"
                         :: "l"(dst),
                            "f"(p[i].x * vv[i]), "f"(p[i].y * vv[i]),
                            "f"(p[i].z * vv[i]), "f"(p[i].w * vv[i])
                         : "memory");
        }
    }
}

// ---------------------------------------------------------------------------
extern "C" void kernel_launch(void* const* d_in, const int* in_sizes, int n_in,
                              void* d_out, int out_size)
{
    const float* emb_node  = (const float*)d_in[0];
    const float* emb_attri = (const float*)d_in[1];
    const float* W1        = (const float*)d_in[2];
    const int*   adj_row   = (const int*)d_in[3];
    const int*   adj_col   = (const int*)d_in[4];
    const float* adj_val   = (const float*)d_in[5];
    const int*   adj2_row  = (const int*)d_in[6];
    const int*   adj2_col  = (const int*)d_in[7];
    const float* adj2_val  = (const float*)d_in[8];

    float* out = (float*)d_out;
    float* x1 = out;
    float* x2 = out + (size_t)N_TOT * NDIM;
    float* x3 = x2  + (size_t)N_TOT * NDIM;

    const int E = in_sizes[3];

    size_t nzero4 = ((size_t)2 * N_TOT * NDIM) >> 2;
    zero_kernel<<<2048, 256>>>(x2, nzero4);

    gemm_kernel<<<(N_TOT + 127) / 128, 256>>>(emb_node, emb_attri, W1, x1);

    const int warpsPerAdj = (E + EPW - 1) / EPW;
    long long totalThreads = (long long)warpsPerAdj * 2 * 32;
    int blocks = (int)((totalThreads + 255) / 256);
    scatter2_kernel<<<blocks, 256>>>(x1, adj_row,  adj_col,  adj_val,
                                         adj2_row, adj2_col, adj2_val,
                                     x2, x3, E);
}